// round 13
// baseline (speedup 1.0000x reference)
#include <cuda_runtime.h>
#include <cstdint>

// SoftNormalShader: gather vertex normals + barycentric interp + softmax RGB blend.
// N=4,H=512,W=512,K=8 ; V=50000, F=100000.
// Inputs (JAX x64 disabled => int arrays are int32):
//   0: verts_normals (V,3) f32   1: bary (P,8,3) f32   2: dists (P,8) f32
//   3: zbuf (P,8) f32            4: faces (F,3) i32    5: pix_to_face (P,8) i32
// Output: (N,H,W,4) float32
//
// R13: LANE-PER-SAMPLE layout. 8 lanes cooperate on one pixel (4 px/warp):
//  - streaming loads are scalar+coalesced (128B per warp-instruction)
//  - zmax / alpha-product via 3-round width-8 shfl_xor reductions
//  - the gather (per-face normal table, L2-resident) executes ONCE per warp
//    with ~4 active lanes in parallel (one per pixel) instead of a serial
//    per-thread loop — GAMMA=1e-4 underflow means ~1.06 of 8 samples pass
//  - tiny register footprint -> full occupancy, no local memory, no smem
// Lazy bary (b2 reconstructed); lane 0 of each group stores the float4.

#define KSAMP 8
#define SIGMA_INV  1e4f
#define GAMMA_INV  1e4f
#define ZFAR_F     100.0f
#define INV_RANGE  (1.0f / 99.0f)
#define EPS_F      1e-10f

#define MAXF 131072

__device__ float4 g_fn[MAXF][3];   // per-face packed vertex normals

__global__ __launch_bounds__(256)
void prep_face_normals_kernel(const float* __restrict__ vn,
                              const int*   __restrict__ faces, int F)
{
    int idx = blockIdx.x * blockDim.x + threadIdx.x;   // (face, vert) pairs
    int f = idx / 3;
    int j = idx - f * 3;
    if (f >= F || f >= MAXF) return;
    int v = __ldg(faces + (long long)f * 3 + j);
    const float* n = vn + (long long)v * 3;
    g_fn[f][j] = make_float4(__ldg(n + 0), __ldg(n + 1), __ldg(n + 2), 0.0f);
}

__global__ __launch_bounds__(256, 8)
void soft_normal_shader_kernel(
    const float* __restrict__ bary,    // (P,8,3)
    const float* __restrict__ dists,   // (P,8)
    const float* __restrict__ zbuf,    // (P,8)
    const int*   __restrict__ p2f,     // (P,8)
    float4*      __restrict__ out,     // (P,) rgba
    int npix)
{
    int t = blockIdx.x * blockDim.x + threadIdx.x;     // one lane per (pixel,sample)
    int pix = t >> 3;
    int k   = t & 7;
    bool live = (pix < npix);
    if (pix >= npix) pix = npix - 1;                   // clamp; keep warp uniform

    const long long si = (long long)pix * KSAMP + k;   // sample index

    // ---- coalesced scalar streaming loads (128B per warp-instruction) ----
    float d = __ldcs(dists + si);
    float z = __ldcs(zbuf  + si);
    int   f = __ldcs(p2f   + si);

    bool valid = f >= 0;
    // sigmoid(-d/SIGMA) = 1/(1+exp(d/SIGMA))
    float p  = valid ? (1.0f / (1.0f + __expf(d * SIGMA_INV))) : 0.0f;
    float zi = valid ? (ZFAR_F - z) * INV_RANGE : 0.0f;

    // ---- width-8 segmented reductions: zmax (max), alpha product ----
    float zmax = zi;
    float om   = 1.0f - p;
    #pragma unroll
    for (int off = 1; off < 8; off <<= 1) {
        zmax = fmaxf(zmax, __shfl_xor_sync(0xFFFFFFFFu, zmax, off));
        om  *=            __shfl_xor_sync(0xFFFFFFFFu, om,   off);
    }

    // ---- per-lane weight; gather only where w > 0 (~1.06 of 8 lanes) ----
    float w = p * __expf((zi - zmax) * GAMMA_INV);   // exact 0 when underflowed
    float accr = 0.0f, accg = 0.0f, accb = 0.0f;
    if (w > 0.0f) {
        // lazy bary: b0,b1 loaded; b2 reconstructed (barycentrics sum to 1)
        const float* bp = bary + si * 3;
        float b0 = __ldg(bp + 0);
        float b1 = __ldg(bp + 1);
        float b2 = 1.0f - b0 - b1;
        // single-hop gather: per-face packed normals (L2-resident)
        const float4* fn = g_fn[f];
        float4 n0 = __ldg(fn + 0);
        float4 n1 = __ldg(fn + 1);
        float4 n2 = __ldg(fn + 2);
        accr = w * (b0 * n0.x + b1 * n1.x + b2 * n2.x);
        accg = w * (b0 * n0.y + b1 * n1.y + b2 * n2.y);
        accb = w * (b0 * n0.z + b1 * n1.z + b2 * n2.z);
    }

    // ---- width-8 sum reductions: wsum + weighted color ----
    float wsum = w;
    #pragma unroll
    for (int off = 1; off < 8; off <<= 1) {
        wsum += __shfl_xor_sync(0xFFFFFFFFu, wsum, off);
        accr += __shfl_xor_sync(0xFFFFFFFFu, accr, off);
        accg += __shfl_xor_sync(0xFFFFFFFFu, accg, off);
        accb += __shfl_xor_sync(0xFFFFFFFFu, accb, off);
    }

    // ---- blend + store (group leader) ----
    if (k == 0 && live) {
        float delta = fmaxf(__expf((EPS_F - zmax) * GAMMA_INV), EPS_F);
        float inv_denom = 1.0f / (wsum + delta);
        float4 o;
        o.x = (accr + delta) * inv_denom;   // background = (1,1,1)
        o.y = (accg + delta) * inv_denom;
        o.z = (accb + delta) * inv_denom;
        o.w = 1.0f - om;                    // 1 - alpha
        __stcs(out + pix, o);
    }
}

extern "C" void kernel_launch(void* const* d_in, const int* in_sizes, int n_in,
                              void* d_out, int out_size)
{
    const float* vn    = (const float*)d_in[0];
    const float* bary  = (const float*)d_in[1];
    const float* dists = (const float*)d_in[2];
    const float* zbuf  = (const float*)d_in[3];
    const int*   faces = (const int*)d_in[4];
    const int*   p2f   = (const int*)d_in[5];
    float4*      out   = (float4*)d_out;

    int F = in_sizes[4] / 3;
    int npix = in_sizes[2] / KSAMP;   // N*H*W

    prep_face_normals_kernel<<<(3 * F + 255) / 256, 256>>>(vn, faces, F);

    long long total = (long long)npix * KSAMP;         // one lane per sample
    int threads = 256;
    int blocks = (int)((total + threads - 1) / threads);
    soft_normal_shader_kernel<<<blocks, threads>>>(bary, dists, zbuf, p2f, out, npix);
}

// round 14
// speedup vs baseline: 1.6638x; 1.6638x over previous
#include <cuda_runtime.h>
#include <cstdint>

// SoftNormalShader: gather vertex normals + barycentric interp + softmax RGB blend.
// N=4,H=512,W=512,K=8 ; V=50000, F=100000.
// Inputs (JAX x64 disabled => int arrays are int32):
//   0: verts_normals (V,3) f32   1: bary (P,8,3) f32   2: dists (P,8) f32
//   3: zbuf (P,8) f32            4: faces (F,3) i32    5: pix_to_face (P,8) i32
// Output: (N,H,W,4) float32
//
// R14: R7 shape (2 px/thread, front-batched __ldcs, lb(256,5)) + SPECULATIVE
// ARGMAX GATHER: the zmax sample always has weight pm[kstar]*exp(0), and ~94%
// of pixels have ONLY that sample pass (GAMMA=1e-4 underflow). Pass 1 tracks
// (zmax,kstar,fstar,pstar) with static selects; the star gather issues right
// after pass 1 (overlapping the alpha-product math), skipping mask/ffs/exp on
// the common path. Rare extra samples (~6% of pixels) go through a select-tree
// while(mask) loop (no dynamic array indexing => no local memory).

#define KSAMP 8
#define SIGMA_INV  1e4f
#define GAMMA_INV  1e4f
#define ZFAR_F     100.0f
#define INV_RANGE  (1.0f / 99.0f)
#define EPS_F      1e-10f

#define MAXF 131072

__device__ float4 g_fn[MAXF][3];   // per-face packed vertex normals

__global__ __launch_bounds__(256)
void prep_face_normals_kernel(const float* __restrict__ vn,
                              const int*   __restrict__ faces, int F)
{
    int idx = blockIdx.x * blockDim.x + threadIdx.x;   // (face, vert) pairs
    int f = idx / 3;
    int j = idx - f * 3;
    if (f >= F || f >= MAXF) return;
    int v = __ldg(faces + (long long)f * 3 + j);
    const float* n = vn + (long long)v * 3;
    g_fn[f][j] = make_float4(__ldg(n + 0), __ldg(n + 1), __ldg(n + 2), 0.0f);
}

// 7-select binary trees: dynamic k -> register value, no local memory.
__device__ __forceinline__ float sel8f(const float* v, int k) {
    float x01 = (k & 1) ? v[1] : v[0];
    float x23 = (k & 1) ? v[3] : v[2];
    float x45 = (k & 1) ? v[5] : v[4];
    float x67 = (k & 1) ? v[7] : v[6];
    float y0  = (k & 2) ? x23 : x01;
    float y1  = (k & 2) ? x67 : x45;
    return (k & 4) ? y1 : y0;
}
__device__ __forceinline__ int sel8i(const int* v, int k) {
    int x01 = (k & 1) ? v[1] : v[0];
    int x23 = (k & 1) ? v[3] : v[2];
    int x45 = (k & 1) ? v[5] : v[4];
    int x67 = (k & 1) ? v[7] : v[6];
    int y0  = (k & 2) ? x23 : x01;
    int y1  = (k & 2) ? x67 : x45;
    return (k & 4) ? y1 : y0;
}

#define PIX_PER_THREAD 2

__global__ __launch_bounds__(256, 5)
void soft_normal_shader_kernel(
    const float* __restrict__ bary,    // (P,8,3)
    const float* __restrict__ dists,   // (P,8)
    const float* __restrict__ zbuf,    // (P,8)
    const int*   __restrict__ p2f,     // (P,8)
    float4*      __restrict__ out,     // (P,) rgba
    int npix)
{
    int tid = blockIdx.x * blockDim.x + threadIdx.x;
    int nthreads = gridDim.x * blockDim.x;

    float4 dv[PIX_PER_THREAD][2], zv[PIX_PER_THREAD][2];
    int4   pv[PIX_PER_THREAD][2];

    // ---- front-batched streaming loads for both pixels (12 x 16B in flight) ----
    #pragma unroll
    for (int j = 0; j < PIX_PER_THREAD; j++) {
        int pix = tid + j * nthreads;
        if (pix >= npix) pix = npix - 1;           // safe clamp (grid is exact anyway)
        const long long base = (long long)pix * KSAMP;
        const float4* dp = reinterpret_cast<const float4*>(dists + base);
        const float4* zp = reinterpret_cast<const float4*>(zbuf  + base);
        const int4*   pp = reinterpret_cast<const int4*>(p2f + base);
        dv[j][0] = __ldcs(dp + 0); dv[j][1] = __ldcs(dp + 1);
        zv[j][0] = __ldcs(zp + 0); zv[j][1] = __ldcs(zp + 1);
        pv[j][0] = __ldcs(pp + 0); pv[j][1] = __ldcs(pp + 1);
    }

    #pragma unroll
    for (int j = 0; j < PIX_PER_THREAD; j++) {
        int pix = tid + j * nthreads;
        if (pix >= npix) continue;
        const long long base = (long long)pix * KSAMP;

        // statically-indexed register views (unrolled access only)
        float df[KSAMP] = { dv[j][0].x, dv[j][0].y, dv[j][0].z, dv[j][0].w,
                            dv[j][1].x, dv[j][1].y, dv[j][1].z, dv[j][1].w };
        float zf[KSAMP] = { zv[j][0].x, zv[j][0].y, zv[j][0].z, zv[j][0].w,
                            zv[j][1].x, zv[j][1].y, zv[j][1].z, zv[j][1].w };
        int   pf[KSAMP] = { pv[j][0].x, pv[j][0].y, pv[j][0].z, pv[j][0].w,
                            pv[j][1].x, pv[j][1].y, pv[j][1].z, pv[j][1].w };

        // ---- pass 1: sigmoid probs, z_inv, alpha product + ARGMAX tracking ----
        float pm[KSAMP], zi[KSAMP];
        float zmax = 0.0f;                 // z_inv >= 0 (masked entries are 0)
        float one_minus_prod = 1.0f;
        int   kstar = -1, fstar = -1;
        float pstar = 0.0f;
        #pragma unroll
        for (int k = 0; k < KSAMP; k++) {
            bool valid = pf[k] >= 0;
            float p = valid ? (1.0f / (1.0f + __expf(df[k] * SIGMA_INV))) : 0.0f;
            pm[k] = p;
            one_minus_prod *= (1.0f - p);
            zi[k] = valid ? (ZFAR_F - zf[k]) * INV_RANGE : 0.0f;
            if (zi[k] > zmax) {            // static k: selects, no local memory
                zmax  = zi[k];
                kstar = k;
                fstar = pf[k];
                pstar = p;
            }
        }

        // ---- speculative star gather: w = pstar (exp(0)==1), issues early ----
        float wsum = 0.0f;
        float accr = 0.0f, accg = 0.0f, accb = 0.0f;
        if (fstar >= 0) {
            const float* bp = bary + (base + kstar) * 3;
            float b0 = __ldg(bp + 0);
            float b1 = __ldg(bp + 1);
            const float4* fn = g_fn[fstar];
            float4 n0 = __ldg(fn + 0);
            float4 n1 = __ldg(fn + 1);
            float4 n2 = __ldg(fn + 2);
            float b2 = 1.0f - b0 - b1;     // barycentrics sum to 1
            wsum = pstar;
            accr = pstar * (b0 * n0.x + b1 * n1.x + b2 * n2.x);
            accg = pstar * (b0 * n0.y + b1 * n1.y + b2 * n2.y);
            accb = pstar * (b0 * n0.z + b1 * n1.z + b2 * n2.z);
        }

        // ---- extras mask: other samples whose exp doesn't flush to 0 (~6%) ----
        unsigned mask = 0;
        #pragma unroll
        for (int k = 0; k < KSAMP; k++) {
            if (pf[k] >= 0 && k != kstar && (zi[k] - zmax) * GAMMA_INV > -88.0f)
                mask |= (1u << k);
        }

        // ---- rare extras loop (select trees; no dynamic array indexing) ----
        while (mask) {
            int k = __ffs(mask) - 1;
            mask &= mask - 1;
            float z = sel8f(zi, k);
            float p = sel8f(pm, k);
            int   f = sel8i(pf, k);
            float w = p * __expf((z - zmax) * GAMMA_INV);
            wsum += w;
            const float* bp = bary + (base + k) * 3;
            float b0 = __ldg(bp + 0);
            float b1 = __ldg(bp + 1);
            float b2 = 1.0f - b0 - b1;
            const float4* fn = g_fn[f];
            float4 n0 = __ldg(fn + 0);
            float4 n1 = __ldg(fn + 1);
            float4 n2 = __ldg(fn + 2);
            accr += w * (b0 * n0.x + b1 * n1.x + b2 * n2.x);
            accg += w * (b0 * n0.y + b1 * n1.y + b2 * n2.y);
            accb += w * (b0 * n0.z + b1 * n1.z + b2 * n2.z);
        }

        // ---- blend ----
        float delta = fmaxf(__expf((EPS_F - zmax) * GAMMA_INV), EPS_F);
        float inv_denom = 1.0f / (wsum + delta);
        float4 o;
        o.x = (accr + delta) * inv_denom;   // background = (1,1,1)
        o.y = (accg + delta) * inv_denom;
        o.z = (accb + delta) * inv_denom;
        o.w = 1.0f - one_minus_prod;        // 1 - alpha
        __stcs(out + pix, o);
    }
}

extern "C" void kernel_launch(void* const* d_in, const int* in_sizes, int n_in,
                              void* d_out, int out_size)
{
    const float* vn    = (const float*)d_in[0];
    const float* bary  = (const float*)d_in[1];
    const float* dists = (const float*)d_in[2];
    const float* zbuf  = (const float*)d_in[3];
    const int*   faces = (const int*)d_in[4];
    const int*   p2f   = (const int*)d_in[5];
    float4*      out   = (float4*)d_out;

    int F = in_sizes[4] / 3;
    int npix = in_sizes[2] / KSAMP;   // N*H*W

    prep_face_normals_kernel<<<(3 * F + 255) / 256, 256>>>(vn, faces, F);

    int threads = 256;
    int total_threads = (npix + PIX_PER_THREAD - 1) / PIX_PER_THREAD;
    int blocks = (total_threads + threads - 1) / threads;
    soft_normal_shader_kernel<<<blocks, threads>>>(bary, dists, zbuf, p2f, out, npix);
}

// round 15
// speedup vs baseline: 1.9356x; 1.1634x over previous
#include <cuda_runtime.h>
#include <cstdint>

// SoftNormalShader: gather vertex normals + barycentric interp + softmax RGB blend.
// N=4,H=512,W=512,K=8 ; V=50000, F=100000.
// Inputs (JAX x64 disabled => int arrays are int32):
//   0: verts_normals (V,3) f32   1: bary (P,8,3) f32   2: dists (P,8) f32
//   3: zbuf (P,8) f32            4: faces (F,3) i32    5: pix_to_face (P,8) i32
// Output: (N,H,W,4) float32
//
// R15: R7 structure (2 px/thread, front-batched __ldcs, lb(256,5), per-face
// normal table, lazy bary, compacted while(mask) loop) + MUFU-count reduction
// (theory: XU pipe is the hidden bottleneck the roofline summary omits):
//   - alpha product via  exp(sum x_k) / prod(1+e_k)  : 8 RCP -> 1 exp + 1 RCP
//   - per-sample sigmoid RCP only for passing samples (~1.06 of 8)
//   - weight exp skipped when arg == 0 (the zmax sample; expf(0)==1 exactly)
//   - delta exp skipped when it provably flushes below EPS (bit-exact)
// MUFU/pixel: ~19 -> ~12.

#define KSAMP 8
#define SIGMA_INV  1e4f
#define GAMMA_INV  1e4f
#define ZFAR_F     100.0f
#define INV_RANGE  (1.0f / 99.0f)
#define EPS_F      1e-10f

#define MAXF 131072

__device__ float4 g_fn[MAXF][3];   // per-face packed vertex normals

__global__ __launch_bounds__(256)
void prep_face_normals_kernel(const float* __restrict__ vn,
                              const int*   __restrict__ faces, int F)
{
    int idx = blockIdx.x * blockDim.x + threadIdx.x;   // (face, vert) pairs
    int f = idx / 3;
    int j = idx - f * 3;
    if (f >= F || f >= MAXF) return;
    int v = __ldg(faces + (long long)f * 3 + j);
    const float* n = vn + (long long)v * 3;
    g_fn[f][j] = make_float4(__ldg(n + 0), __ldg(n + 1), __ldg(n + 2), 0.0f);
}

#define PIX_PER_THREAD 2

__global__ __launch_bounds__(256, 5)
void soft_normal_shader_kernel(
    const float* __restrict__ bary,    // (P,8,3)
    const float* __restrict__ dists,   // (P,8)
    const float* __restrict__ zbuf,    // (P,8)
    const int*   __restrict__ p2f,     // (P,8)
    float4*      __restrict__ out,     // (P,) rgba
    int npix)
{
    int tid = blockIdx.x * blockDim.x + threadIdx.x;
    int nthreads = gridDim.x * blockDim.x;

    float4 dv[PIX_PER_THREAD][2], zv[PIX_PER_THREAD][2];
    int4   pv[PIX_PER_THREAD][2];

    // ---- front-batched streaming loads for both pixels (12 x 16B in flight) ----
    #pragma unroll
    for (int j = 0; j < PIX_PER_THREAD; j++) {
        int pix = tid + j * nthreads;
        if (pix >= npix) pix = npix - 1;           // safe clamp (grid is exact anyway)
        const long long base = (long long)pix * KSAMP;
        const float4* dp = reinterpret_cast<const float4*>(dists + base);
        const float4* zp = reinterpret_cast<const float4*>(zbuf  + base);
        const int4*   pp = reinterpret_cast<const int4*>(p2f + base);
        dv[j][0] = __ldcs(dp + 0); dv[j][1] = __ldcs(dp + 1);
        zv[j][0] = __ldcs(zp + 0); zv[j][1] = __ldcs(zp + 1);
        pv[j][0] = __ldcs(pp + 0); pv[j][1] = __ldcs(pp + 1);
    }

    #pragma unroll
    for (int j = 0; j < PIX_PER_THREAD; j++) {
        int pix = tid + j * nthreads;
        if (pix >= npix) continue;
        const long long base = (long long)pix * KSAMP;

        // statically-indexed register views
        float df[KSAMP] = { dv[j][0].x, dv[j][0].y, dv[j][0].z, dv[j][0].w,
                            dv[j][1].x, dv[j][1].y, dv[j][1].z, dv[j][1].w };
        float zf[KSAMP] = { zv[j][0].x, zv[j][0].y, zv[j][0].z, zv[j][0].w,
                            zv[j][1].x, zv[j][1].y, zv[j][1].z, zv[j][1].w };
        int   pf[KSAMP] = { pv[j][0].x, pv[j][0].y, pv[j][0].z, pv[j][0].w,
                            pv[j][1].x, pv[j][1].y, pv[j][1].z, pv[j][1].w };

        // ---- pass 1: e_k = exp(x_k); alpha via exp(sum)/prod; zmax ----
        // (1 - sigmoid(-x)) = e^x / (1+e^x)  =>  prod = exp(sum x) / prod(1+e)
        float ex[KSAMP], zi[KSAMP];
        float xsum = 0.0f, qprod = 1.0f;
        float zmax = 0.0f;                 // z_inv >= 0 (masked entries are 0)
        #pragma unroll
        for (int k = 0; k < KSAMP; k++) {
            bool valid = pf[k] >= 0;
            float x = df[k] * SIGMA_INV;
            float e = __expf(x);
            ex[k] = e;
            xsum  += valid ? x : 0.0f;
            qprod *= valid ? (1.0f + e) : 1.0f;
            zi[k] = valid ? (ZFAR_F - zf[k]) * INV_RANGE : 0.0f;
            zmax = fmaxf(zmax, zi[k]);
        }
        float one_minus_prod = __expf(xsum) / qprod;   // 1 exp + 1 rcp

        // ---- candidate mask: exp((z-zmax)*1e4) flushes to 0 below ~-88 ----
        unsigned mask = 0;
        #pragma unroll
        for (int k = 0; k < KSAMP; k++) {
            if (pf[k] >= 0 && (zi[k] - zmax) * GAMMA_INV > -88.0f)
                mask |= (1u << k);
        }

        // ---- compacted weight + gather loop (~1.06 iterations) ----
        float wsum = 0.0f;
        float accr = 0.0f, accg = 0.0f, accb = 0.0f;
        while (mask) {
            int k = __ffs(mask) - 1;
            mask &= mask - 1;
            float e2 = (zi[k] - zmax) * GAMMA_INV;
            float wm = 1.0f;                 // expf(0)==1 exactly (zmax sample)
            if (e2 != 0.0f) wm = __expf(e2); // rare extra samples only
            float p = 1.0f / (1.0f + ex[k]); // sigmoid RCP only where needed
            float w = p * wm;
            wsum += w;
            // lazy bary: b0,b1 loaded; b2 reconstructed (sum == 1)
            const float* bp = bary + (base + k) * 3;
            float b0 = __ldg(bp + 0);
            float b1 = __ldg(bp + 1);
            float b2 = 1.0f - b0 - b1;
            // single-hop gather: per-face packed normals (L2-resident)
            const float4* fn = g_fn[pf[k]];
            float4 n0 = __ldg(fn + 0);
            float4 n1 = __ldg(fn + 1);
            float4 n2 = __ldg(fn + 2);
            accr += w * (b0 * n0.x + b1 * n1.x + b2 * n2.x);
            accg += w * (b0 * n0.y + b1 * n1.y + b2 * n2.y);
            accb += w * (b0 * n0.z + b1 * n1.z + b2 * n2.z);
        }

        // ---- blend; delta exp skipped when it provably flushes under EPS ----
        float darg = (EPS_F - zmax) * GAMMA_INV;
        float delta = EPS_F;
        if (darg > -88.0f)                   // ~never taken (zmax ~ 0.9)
            delta = fmaxf(__expf(darg), EPS_F);
        float inv_denom = 1.0f / (wsum + delta);
        float4 o;
        o.x = (accr + delta) * inv_denom;   // background = (1,1,1)
        o.y = (accg + delta) * inv_denom;
        o.z = (accb + delta) * inv_denom;
        o.w = 1.0f - one_minus_prod;        // 1 - alpha
        __stcs(out + pix, o);
    }
}

extern "C" void kernel_launch(void* const* d_in, const int* in_sizes, int n_in,
                              void* d_out, int out_size)
{
    const float* vn    = (const float*)d_in[0];
    const float* bary  = (const float*)d_in[1];
    const float* dists = (const float*)d_in[2];
    const float* zbuf  = (const float*)d_in[3];
    const int*   faces = (const int*)d_in[4];
    const int*   p2f   = (const int*)d_in[5];
    float4*      out   = (float4*)d_out;

    int F = in_sizes[4] / 3;
    int npix = in_sizes[2] / KSAMP;   // N*H*W

    prep_face_normals_kernel<<<(3 * F + 255) / 256, 256>>>(vn, faces, F);

    int threads = 256;
    int total_threads = (npix + PIX_PER_THREAD - 1) / PIX_PER_THREAD;
    int blocks = (total_threads + threads - 1) / threads;
    soft_normal_shader_kernel<<<blocks, threads>>>(bary, dists, zbuf, p2f, out, npix);
}